// round 5
// baseline (speedup 1.0000x reference)
#include <cuda_runtime.h>

// Denoise_17669495455833: batched FISTA QP (2 passes x 100 iters, rows of 512 fp32).
// R5: latency-bound at occ=17.6% (regs=148 -> 12 warps/SM), fma pipe 68.6% is the wall.
//  - Cap regs at 128 via __launch_bounds__(128,4) -> 16 warps/SM.
//  - DtD as double second-difference with zero-padding: d_i = z_i - 2 z_{i+1} + z_{i+2},
//    a_j = d_{j-2} - 2 d_{j-1} + d_j (out-of-range d = 0). Removes all boundary special
//    cases and 3 constants. Identical math to the reference's pad-and-adjoint.
//  - Still packed f32x2 over two independent rows per warp; clip = scalar FMNMX (alu pipe).

typedef unsigned long long u64;
#define FULL_MASK 0xffffffffu

__device__ u64 g_coefs[100];   // packed (coef, coef) per iteration

__device__ __forceinline__ u64 pk2(float lo, float hi) {
    u64 r;
    asm("mov.b64 %0, {%1,%2};" : "=l"(r) : "r"(__float_as_uint(lo)), "r"(__float_as_uint(hi)));
    return r;
}
__device__ __forceinline__ void upk2(u64 v, float& lo, float& hi) {
    unsigned a, b;
    asm("mov.b64 {%0,%1}, %2;" : "=r"(a), "=r"(b) : "l"(v));
    lo = __uint_as_float(a); hi = __uint_as_float(b);
}
__device__ __forceinline__ u64 fma2(u64 a, u64 b, u64 c) {
    u64 d;
    asm("fma.rn.f32x2 %0, %1, %2, %3;" : "=l"(d) : "l"(a), "l"(b), "l"(c));
    return d;
}
__device__ __forceinline__ u64 add2(u64 a, u64 b) {
    u64 d;
    asm("add.rn.f32x2 %0, %1, %2;" : "=l"(d) : "l"(a), "l"(b));
    return d;
}
__device__ __forceinline__ u64 rep2(float f) {
    unsigned u = __float_as_uint(f);
    return ((u64)u << 32) | (u64)u;
}

__global__ void coef_setup_kernel() {
    if (threadIdx.x == 0 && blockIdx.x == 0) {
        float t = 1.0f;
        for (int i = 0; i < 100; ++i) {
            float tn = 0.5f * (1.0f + sqrtf(fmaf(4.0f * t, t, 1.0f)));
            float c  = (t - 1.0f) / tn;
            unsigned u = __float_as_uint(c);
            g_coefs[i] = ((u64)u << 32) | (u64)u;
            t = tn;
        }
    }
}

__global__ void __launch_bounds__(128, 4)
denoise_fista3_kernel(const float* __restrict__ in, float* __restrict__ out, int nrows)
{
    const int gw   = (int)((blockIdx.x * blockDim.x + threadIdx.x) >> 5);  // warp = row pair
    const int lane = (int)(threadIdx.x & 31);
    if (gw * 2 + 1 >= nrows) return;

    const float* rA = in + (size_t)(gw * 2)     * 512 + lane * 16;
    const float* rB = in + (size_t)(gw * 2 + 1) * 512 + lane * 16;

    u64 y[16], x[16], z[16];
    #pragma unroll
    for (int i = 0; i < 16; i += 4) {
        float4 a4 = *reinterpret_cast<const float4*>(rA + i);
        float4 b4 = *reinterpret_cast<const float4*>(rB + i);
        y[i + 0] = pk2(a4.x, b4.x);
        y[i + 1] = pk2(a4.y, b4.y);
        y[i + 2] = pk2(a4.z, b4.z);
        y[i + 3] = pk2(a4.w, b4.w);
    }

    // LAM = 10, step = 1/(2*(1+16*LAM)) = 1/322
    const float STEP = 1.0f / 322.0f;
    const u64 C_M2  = rep2(-2.0f);
    const u64 NEG1  = rep2(-1.0f);
    const u64 C_ZY  = rep2(-2.0f * STEP);           // coeff of (z - y)
    const u64 C_DT  = rep2(-2.0f * 10.0f * STEP);   // coeff of DtD(z)
    const bool first = (lane == 0);
    const bool last  = (lane == 31);

    #pragma unroll 1
    for (int pass = 0; pass < 2; ++pass) {
        #pragma unroll
        for (int k = 0; k < 16; ++k) { x[k] = y[k]; z[k] = y[k]; }   // x0 = proj(y) = y

        #pragma unroll 1
        for (int it = 0; it < 100; ++it) {
            // neighbor pairs from the previous iterate (warp-synchronous)
            u64 zm2 = __shfl_up_sync  (FULL_MASK, z[14], 1);
            u64 zm1 = __shfl_up_sync  (FULL_MASK, z[15], 1);
            u64 zp0 = __shfl_down_sync(FULL_MASK, z[0],  1);
            u64 zp1 = __shfl_down_sync(FULL_MASK, z[1],  1);

            const u64 coefP = g_coefs[it];

            // rotating window of second differences d_i = z_i - 2 z_{i+1} + z_{i+2}
            // (out-of-range d = 0: handles BOTH boundary rows of DtD exactly)
            u64 dm2 = first ? 0ULL : add2(fma2(zm1,  C_M2, zm2), z[0]);   // d[base-2]
            u64 dm1 = first ? 0ULL : add2(fma2(z[0], C_M2, zm1), z[1]);   // d[base-1]

            #pragma unroll
            for (int k = 0; k < 16; ++k) {
                u64 za = z[k];
                u64 zb = (k < 15) ? z[k + 1] : zp0;
                u64 zc = (k < 14) ? z[k + 2] : ((k == 14) ? zp0 : zp1);

                u64 dcur = add2(fma2(zb, C_M2, za), zc);
                if (k >= 14) dcur = last ? 0ULL : dcur;   // d beyond n-3 is zero

                // a = DtD(z)_j = d[j-2] - 2 d[j-1] + d[j]
                u64 a = add2(fma2(dm1, C_M2, dm2), dcur);

                // v = z + C_ZY*(z - y) + C_DT*a
                u64 diff = fma2(y[k], NEG1, za);
                u64 v = fma2(diff, C_ZY, za);
                v     = fma2(a,    C_DT, v);

                // x_new = clip(v, 0, y)  (scalar FMNMX -> alu pipe)
                float vlo, vhi, ylo, yhi;
                upk2(v, vlo, vhi);
                upk2(y[k], ylo, yhi);
                float xlo = fminf(fmaxf(vlo, 0.0f), ylo);
                float xhi = fminf(fmaxf(vhi, 0.0f), yhi);
                u64 xn = pk2(xlo, xhi);

                // z_new = x_new + coef*(x_new - x)
                u64 dx = fma2(x[k], NEG1, xn);
                z[k] = fma2(dx, coefP, xn);
                x[k] = xn;

                dm2 = dm1; dm1 = dcur;
            }
        }

        if (pass == 0) {
            #pragma unroll
            for (int k = 0; k < 16; ++k) y[k] = x[k];   // pass 2: y = pass-1 output
        }
    }

    float* oA = out + (size_t)(gw * 2)     * 512 + lane * 16;
    float* oB = out + (size_t)(gw * 2 + 1) * 512 + lane * 16;
    #pragma unroll
    for (int i = 0; i < 16; i += 4) {
        float4 a4, b4;
        upk2(x[i + 0], a4.x, b4.x);
        upk2(x[i + 1], a4.y, b4.y);
        upk2(x[i + 2], a4.z, b4.z);
        upk2(x[i + 3], a4.w, b4.w);
        *reinterpret_cast<float4*>(oA + i) = a4;
        *reinterpret_cast<float4*>(oB + i) = b4;
    }
}

extern "C" void kernel_launch(void* const* d_in, const int* in_sizes, int n_in,
                              void* d_out, int out_size)
{
    const float* in  = (const float*)d_in[0];
    float*       out = (float*)d_out;
    const int nrows  = in_sizes[0] / 512;            // 16384 rows
    coef_setup_kernel<<<1, 32>>>();
    const int warps  = nrows / 2;                    // 2 rows per warp
    const int blocks = (warps + 3) / 4;              // 4 warps per block
    denoise_fista3_kernel<<<blocks, 128>>>(in, out, nrows);
}

// round 8
// speedup vs baseline: 1.0750x; 1.0750x over previous
#include <cuda_runtime.h>

// Denoise_17669495455833: batched FISTA QP (2 passes x 100 iters, rows of 512 fp32).
// R7: R6's precombined pentadiagonal stencil (rt2 add2/mul2/sub2 + rt3 fma2) with the
// CRITICAL fix: left stencil neighbors come from a rotating window of OLD z values
// (p2, p1), since z[k] is overwritten in place as k ascends. R6 read updated values
// (Gauss-Seidel contamination -> rel_err 0.78).
//   v_j = CA z_j + CB (z_{j-1}+z_{j+1}) + CC (z_{j-2}+z_{j+2}) + CE y_j   (zero-padded)
//   + predicated corrections at j in {0,1,510,511} for the true DtD boundary rows.

typedef unsigned long long u64;
#define FULL_MASK 0xffffffffu

__device__ u64 g_coefs[100];   // packed (coef, coef) per iteration

__device__ __forceinline__ u64 pk2(float lo, float hi) {
    u64 r;
    asm("mov.b64 %0, {%1,%2};" : "=l"(r) : "r"(__float_as_uint(lo)), "r"(__float_as_uint(hi)));
    return r;
}
__device__ __forceinline__ void upk2(u64 v, float& lo, float& hi) {
    unsigned a, b;
    asm("mov.b64 {%0,%1}, %2;" : "=r"(a), "=r"(b) : "l"(v));
    lo = __uint_as_float(a); hi = __uint_as_float(b);
}
__device__ __forceinline__ u64 fma2(u64 a, u64 b, u64 c) {
    u64 d;
    asm("fma.rn.f32x2 %0, %1, %2, %3;" : "=l"(d) : "l"(a), "l"(b), "l"(c));
    return d;
}
__device__ __forceinline__ u64 add2(u64 a, u64 b) {
    u64 d;
    asm("add.rn.f32x2 %0, %1, %2;" : "=l"(d) : "l"(a), "l"(b));
    return d;
}
__device__ __forceinline__ u64 sub2(u64 a, u64 b) {
    u64 d;
    asm("sub.rn.f32x2 %0, %1, %2;" : "=l"(d) : "l"(a), "l"(b));
    return d;
}
__device__ __forceinline__ u64 mul2(u64 a, u64 b) {
    u64 d;
    asm("mul.rn.f32x2 %0, %1, %2;" : "=l"(d) : "l"(a), "l"(b));
    return d;
}
__device__ __forceinline__ u64 rep2(float f) {
    unsigned u = __float_as_uint(f);
    return ((u64)u << 32) | (u64)u;
}

__global__ void coef_setup_kernel() {
    if (threadIdx.x == 0 && blockIdx.x == 0) {
        float t = 1.0f;
        for (int i = 0; i < 100; ++i) {
            float tn = 0.5f * (1.0f + sqrtf(fmaf(4.0f * t, t, 1.0f)));
            float c  = (t - 1.0f) / tn;
            unsigned u = __float_as_uint(c);
            g_coefs[i] = ((u64)u << 32) | (u64)u;
            t = tn;
        }
    }
}

__global__ void __launch_bounds__(128)
denoise_fista5_kernel(const float* __restrict__ in, float* __restrict__ out, int nrows)
{
    const int gw   = (int)((blockIdx.x * blockDim.x + threadIdx.x) >> 5);  // warp = row pair
    const int lane = (int)(threadIdx.x & 31);
    if (gw * 2 + 1 >= nrows) return;

    const float* rA = in + (size_t)(gw * 2)     * 512 + lane * 16;
    const float* rB = in + (size_t)(gw * 2 + 1) * 512 + lane * 16;

    u64 y[16], x[16], z[16];
    #pragma unroll
    for (int i = 0; i < 16; i += 4) {
        float4 a4 = *reinterpret_cast<const float4*>(rA + i);
        float4 b4 = *reinterpret_cast<const float4*>(rB + i);
        y[i + 0] = pk2(a4.x, b4.x);
        y[i + 1] = pk2(a4.y, b4.y);
        y[i + 2] = pk2(a4.z, b4.z);
        y[i + 3] = pk2(a4.w, b4.w);
    }

    // LAM = 10, step = 1/322.
    // v = z + CZY*(z-y) + CDT*DtD(z),  CZY = -2/322, CDT = -20/322. Precombined:
    const float STEPf = 1.0f / 322.0f;
    const float CZYf  = -2.0f * STEPf;
    const float CDTf  = -2.0f * 10.0f * STEPf;
    const u64 CA = rep2(1.0f + CZYf + 6.0f * CDTf);   // z_j
    const u64 CB = rep2(-4.0f * CDTf);                // z_{j+-1}
    const u64 CC = rep2(CDTf);                        // z_{j+-2}
    const u64 CE = rep2(-CZYf);                       // y_j
    // boundary corrections (true DtD row minus zero-padded interior stencil), x CDT:
    const u64 Q1 = rep2(-5.0f * CDTf);
    const u64 Q2 = rep2( 2.0f * CDTf);
    const u64 Q3 = rep2(-1.0f * CDTf);

    const bool first = (lane == 0);
    const bool last  = (lane == 31);

    #pragma unroll 1
    for (int pass = 0; pass < 2; ++pass) {
        #pragma unroll
        for (int k = 0; k < 16; ++k) { x[k] = y[k]; z[k] = y[k]; }   // x0 = proj(y) = y

        #pragma unroll 1
        for (int it = 0; it < 100; ++it) {
            // neighbor pairs (previous iterate); out-of-range -> 0
            u64 zm2 = __shfl_up_sync  (FULL_MASK, z[14], 1);
            u64 zm1 = __shfl_up_sync  (FULL_MASK, z[15], 1);
            u64 zp1 = __shfl_down_sync(FULL_MASK, z[0],  1);
            u64 zp2 = __shfl_down_sync(FULL_MASK, z[1],  1);
            if (first) { zm2 = 0ULL; zm1 = 0ULL; }
            if (last)  { zp1 = 0ULL; zp2 = 0ULL; }

            const u64 coefP = g_coefs[it];

            // rotating window of OLD z values (z[] is overwritten in place)
            u64 p2 = zm2, p1 = zm1;

            #pragma unroll
            for (int k = 0; k < 16; ++k) {
                u64 zc  = z[k];                                 // old z_j
                u64 zR1 = (k <= 14) ? z[k + 1] : zp1;           // old z_{j+1}
                u64 zR2 = (k <= 13) ? z[k + 2] : ((k == 14) ? zp1 : zp2);  // old z_{j+2}

                u64 s1 = add2(p1, zR1);             // rt2
                u64 s2 = add2(p2, zR2);             // rt2
                u64 v  = mul2(y[k], CE);            // rt2
                v = fma2(zc, CA, v);                // rt3
                v = fma2(s1, CB, v);                // rt3
                v = fma2(s2, CC, v);                // rt3

                // true DtD boundary rows (old values: p1 = old left neighbor)
                if (k == 0) {
                    if (first) { v = fma2(zc, Q1, v); v = fma2(z[1], Q2, v); }
                }
                if (k == 1) {
                    if (first) { v = fma2(p1, Q2, v); v = fma2(zc, Q3, v); }
                }
                if (k == 14) {
                    if (last)  { v = fma2(zc, Q3, v); v = fma2(z[15], Q2, v); }
                }
                if (k == 15) {
                    if (last)  { v = fma2(p1, Q2, v); v = fma2(zc, Q1, v); }
                }

                // x_new = clip(v, 0, y)  (scalar FMNMX -> alu pipe)
                float vlo, vhi, ylo, yhi;
                upk2(v, vlo, vhi);
                upk2(y[k], ylo, yhi);
                float xlo = fminf(fmaxf(vlo, 0.0f), ylo);
                float xhi = fminf(fmaxf(vhi, 0.0f), yhi);
                u64 xn = pk2(xlo, xhi);

                // z_new = x_new + coef*(x_new - x)
                u64 dx = sub2(xn, x[k]);            // rt2
                z[k] = fma2(dx, coefP, xn);         // rt3
                x[k] = xn;

                p2 = p1; p1 = zc;
            }
        }

        if (pass == 0) {
            #pragma unroll
            for (int k = 0; k < 16; ++k) y[k] = x[k];   // pass 2: y = pass-1 output
        }
    }

    float* oA = out + (size_t)(gw * 2)     * 512 + lane * 16;
    float* oB = out + (size_t)(gw * 2 + 1) * 512 + lane * 16;
    #pragma unroll
    for (int i = 0; i < 16; i += 4) {
        float4 a4, b4;
        upk2(x[i + 0], a4.x, b4.x);
        upk2(x[i + 1], a4.y, b4.y);
        upk2(x[i + 2], a4.z, b4.z);
        upk2(x[i + 3], a4.w, b4.w);
        *reinterpret_cast<float4*>(oA + i) = a4;
        *reinterpret_cast<float4*>(oB + i) = b4;
    }
}

extern "C" void kernel_launch(void* const* d_in, const int* in_sizes, int n_in,
                              void* d_out, int out_size)
{
    const float* in  = (const float*)d_in[0];
    float*       out = (float*)d_out;
    const int nrows  = in_sizes[0] / 512;            // 16384 rows
    coef_setup_kernel<<<1, 32>>>();
    const int warps  = nrows / 2;                    // 2 rows per warp
    const int blocks = (warps + 3) / 4;              // 4 warps per block
    denoise_fista5_kernel<<<blocks, 128>>>(in, out, nrows);
}